// round 10
// baseline (speedup 1.0000x reference)
#include <cuda_runtime.h>
#include <cuda_bf16.h>
#include <cstdint>

#define N_NODES 50000
#define E_EDGES 800000
#define NB_STATS 240
#define NB_EDGE 592   // edge kernel grid (4736 warps)

// ---------------- device scratch (static, no allocs) ----------------
// P layout per node (256 floats):
//   dst [0,128):   channel c -> fd at (c>>1)*4+(c&1), sd at +2  (float4/lane = {fd0,fd1,sd0,sd1})
//   src [128,256): same + 128 (fs / ss)
__device__ __align__(16) float  d_P[(size_t)N_NODES * 256];
__device__ __align__(16) float  d_y0[(size_t)N_NODES * 64];
__device__ __align__(16) float  d_y1[(size_t)N_NODES * 64];
__device__ __align__(16) float  d_Wnode[2][64 * 256];
__device__ __align__(16) float  d_WqT[2][128 * 16];    // edge weights [chan][k] (chan<64 f, else s)
__device__ float  d_bias2[2][256];
__device__ float  d_psum[NB_STATS * 64];
__device__ float  d_psq[NB_STATS * 64];
__device__ __align__(16) float  d_scale[2][64];
__device__ __align__(16) float  d_shift[2][64];
__device__ int    d_bound[65];
__device__ int    d_ei64;

__device__ __forceinline__ int idx_fd(int c) { return ((c >> 1) << 2) + (c & 1); }

__device__ __forceinline__ float sigmoid_f(float x) {
    float t;
    asm("tanh.approx.f32 %0, %1;" : "=f"(t) : "f"(x * 0.5f));
    return fmaf(0.5f, t, 0.5f);
}
__device__ __forceinline__ float softplus_f(float x) {
    return (x > 20.f) ? x : __logf(1.f + __expf(x));
}
__device__ __forceinline__ uint64_t fma2(uint64_t a, uint64_t b, uint64_t c) {
    uint64_t d;
    asm("fma.rn.f32x2 %0, %1, %2, %3;" : "=l"(d) : "l"(a), "l"(b), "l"(c));
    return d;
}
__device__ __forceinline__ float2 unpack2(uint64_t v) {
    float2 r;
    asm("mov.b64 {%0, %1}, %2;" : "=f"(r.x), "=f"(r.y) : "l"(v));
    return r;
}

// ---------------- dtype detection + graph bounds (1 block) ----------------
__global__ void detect_bounds_kernel(const int* __restrict__ ei32, const int* __restrict__ b32) {
    __shared__ int sb64;
    if (threadIdx.x == 0) {
        int o = 0;
        #pragma unroll
        for (int i = 1; i < 64; i += 2) o |= ei32[i];
        d_ei64 = (o == 0) ? 1 : 0;
        sb64 = (b32[N_NODES - 1] == 0) ? 1 : 0;
    }
    __syncthreads();
    int g = threadIdx.x;
    if (g <= 64) {
        int b64 = sb64;
        const long long* bL = (const long long*)b32;
        int lo = 0, hi = N_NODES;
        while (lo < hi) {
            int mid = (lo + hi) >> 1;
            long long bv = b64 ? bL[mid] : (long long)b32[mid];
            if (bv < (long long)g) lo = mid + 1; else hi = mid;
        }
        d_bound[g] = lo;
    }
}

// ---------------- prep: pack weights only (tiny) ----------------
__global__ void prep_kernel(const float* __restrict__ Wf0, const float* __restrict__ Ws0,
                            const float* __restrict__ bf0, const float* __restrict__ bs0,
                            const float* __restrict__ Wf1, const float* __restrict__ Ws1,
                            const float* __restrict__ bf1, const float* __restrict__ bs1) {
    int stride = gridDim.x * blockDim.x;
    int gid = blockIdx.x * blockDim.x + threadIdx.x;
    for (int i = gid; i < 2 * 64 * 144; i += stride) {
        int l = i / 9216; int r = i % 9216; int j = r / 144; int k = r % 144;
        const float* Wf = l ? Wf1 : Wf0;
        const float* Ws = l ? Ws1 : Ws0;
        float wf = Wf[j * 144 + k], ws = Ws[j * 144 + k];
        int pf = idx_fd(j);
        if (k < 64) {
            d_Wnode[l][k * 256 + pf]     = wf;
            d_Wnode[l][k * 256 + pf + 2] = ws;
        } else if (k < 128) {
            int kk = k - 64;
            d_Wnode[l][kk * 256 + 128 + pf]     = wf;
            d_Wnode[l][kk * 256 + 128 + pf + 2] = ws;
        } else {
            int kk = k - 128;
            d_WqT[l][j * 16 + kk]        = wf;
            d_WqT[l][(64 + j) * 16 + kk] = ws;
        }
    }
    for (int i = gid; i < 2 * 64; i += stride) {
        int l = i >> 6; int j = i & 63;
        const float* bf = l ? bf1 : bf0;
        const float* bs = l ? bs1 : bs0;
        int pf = idx_fd(j);
        d_bias2[l][pf]           = bf[j];
        d_bias2[l][pf + 2]       = bs[j];
        d_bias2[l][128 + pf]     = 0.f;
        d_bias2[l][128 + pf + 2] = 0.f;
    }
}

// ---------------- node GEMM: P = in @ Wnode + bias; also writes residual into y ----------------
__global__ __launch_bounds__(256, 2) void node_gemm_kernel(const float* __restrict__ x_in, int layer) {
    __shared__ __align__(16) float sX[64 * 68];
    __shared__ float sB[256];
    __shared__ float sSc[64], sSh[64];
    int t = threadIdx.x;
    int n0 = blockIdx.x * 64;
    const float* __restrict__ src = layer ? d_y0 : x_in;
    float* __restrict__ y = layer ? d_y1 : d_y0;
    const float* __restrict__ Wn = d_Wnode[layer];

    sB[t] = d_bias2[layer][t];
    if (t < 64) {
        sSc[t] = layer ? d_scale[0][t] : 1.f;
        sSh[t] = layer ? d_shift[0][t] : 0.f;
    }
    __syncthreads();
    {
        int n = t >> 2, q = t & 3;
        int node = n0 + n;
        #pragma unroll
        for (int i = 0; i < 4; i++) {
            int k = q * 16 + i * 4;
            float4 v = make_float4(0.f, 0.f, 0.f, 0.f);
            if (node < N_NODES) v = *(const float4*)&src[(size_t)node * 64 + k];
            float4 w = make_float4(v.x * sSc[k + 0] + sSh[k + 0],
                                   v.y * sSc[k + 1] + sSh[k + 1],
                                   v.z * sSc[k + 2] + sSh[k + 2],
                                   v.w * sSc[k + 3] + sSh[k + 3]);
            sX[(k + 0) * 68 + n] = w.x;
            sX[(k + 1) * 68 + n] = w.y;
            sX[(k + 2) * 68 + n] = w.z;
            sX[(k + 3) * 68 + n] = w.w;
            if (node < N_NODES) *(float4*)&y[(size_t)node * 64 + k] = w;  // residual init
        }
    }
    __syncthreads();

    int tx = t & 31, ty = t >> 5;
    float acc[8][8];
    #pragma unroll
    for (int e = 0; e < 8; e++)
        #pragma unroll
        for (int j = 0; j < 8; j++) acc[e][j] = 0.f;

    #pragma unroll 8
    for (int k = 0; k < 64; k++) {
        float4 w0 = *(const float4*)&Wn[k * 256 + tx * 8];
        float4 w1 = *(const float4*)&Wn[k * 256 + tx * 8 + 4];
        float4 z0 = *(const float4*)&sX[k * 68 + ty * 8];
        float4 z1 = *(const float4*)&sX[k * 68 + ty * 8 + 4];
        float ww[8] = {w0.x, w0.y, w0.z, w0.w, w1.x, w1.y, w1.z, w1.w};
        float zz[8] = {z0.x, z0.y, z0.z, z0.w, z1.x, z1.y, z1.z, z1.w};
        #pragma unroll
        for (int e = 0; e < 8; e++)
            #pragma unroll
            for (int j = 0; j < 8; j++) acc[e][j] += zz[e] * ww[j];
    }

    float b[8];
    #pragma unroll
    for (int j = 0; j < 8; j++) b[j] = sB[tx * 8 + j];
    #pragma unroll
    for (int e = 0; e < 8; e++) {
        int node = n0 + ty * 8 + e;
        if (node < N_NODES) {
            float4 o0 = make_float4(acc[e][0] + b[0], acc[e][1] + b[1], acc[e][2] + b[2], acc[e][3] + b[3]);
            float4 o1 = make_float4(acc[e][4] + b[4], acc[e][5] + b[5], acc[e][6] + b[6], acc[e][7] + b[7]);
            *(float4*)&d_P[(size_t)node * 256 + tx * 8]     = o0;
            *(float4*)&d_P[(size_t)node * 256 + tx * 8 + 4] = o1;
        }
    }
}

// ---------------- edge kernel: warp = 1 edge, lane = 2 channels, vector RED scatter ----------------
__global__ __launch_bounds__(256) void edge_kernel(const void* __restrict__ ei_raw,
                                                   const float* __restrict__ ea, int layer) {
    const float* __restrict__ WqT = d_WqT[layer];
    float* __restrict__ y = layer ? d_y1 : d_y0;
    int tid = threadIdx.x, warp = tid >> 5, lane = tid & 31;
    int gw = blockIdx.x * 8 + warp;
    const int nw = NB_EDGE * 8;
    int c0 = lane * 2;
    const int ei64 = d_ei64;
    const long long* eL = (const long long*)ei_raw;
    const int*       eI = (const int*)ei_raw;

    // per-lane weights: f/s rows for channels c0, c0+1, as k-pairs (32 u64)
    uint64_t wf0[8], wf1[8], ws0[8], ws1[8];
    {
        const uint64_t* W0 = (const uint64_t*)&WqT[c0 * 16];
        const uint64_t* W1 = (const uint64_t*)&WqT[(c0 + 1) * 16];
        const uint64_t* W2 = (const uint64_t*)&WqT[(64 + c0) * 16];
        const uint64_t* W3 = (const uint64_t*)&WqT[(65 + c0) * 16];
        #pragma unroll
        for (int k = 0; k < 8; k++) { wf0[k] = W0[k]; wf1[k] = W1[k]; ws0[k] = W2[k]; ws1[k] = W3[k]; }
    }

    for (int e = gw; e < E_EDGES; e += nw) {
        int s, d;
        if (ei64) { s = (int)eL[e]; d = (int)eL[E_EDGES + e]; }
        else      { s = eI[e];      d = eI[E_EDGES + e]; }
        s = min(max(s, 0), N_NODES - 1);
        d = min(max(d, 0), N_NODES - 1);

        float4 dp = *(const float4*)&d_P[(size_t)d * 256 + lane * 4];        // {fd0,fd1,sd0,sd1}
        float4 sp = *(const float4*)&d_P[(size_t)s * 256 + 128 + lane * 4];  // {fs0,fs1,ss0,ss1}
        const ulonglong2* A = (const ulonglong2*)&ea[(size_t)e * 16];
        ulonglong2 u0 = A[0], u1 = A[1], u2 = A[2], u3 = A[3];
        uint64_t ep[8] = {u0.x, u0.y, u1.x, u1.y, u2.x, u2.y, u3.x, u3.y};

        uint64_t qf0 = 0, qf1 = 0, qs0 = 0, qs1 = 0;
        #pragma unroll
        for (int k = 0; k < 8; k++) {
            qf0 = fma2(wf0[k], ep[k], qf0);
            qf1 = fma2(wf1[k], ep[k], qf1);
            qs0 = fma2(ws0[k], ep[k], qs0);
            qs1 = fma2(ws1[k], ep[k], qs1);
        }
        float2 h0 = unpack2(qf0), h1 = unpack2(qf1), h2 = unpack2(qs0), h3 = unpack2(qs1);
        float f0 = dp.x + sp.x + (h0.x + h0.y);
        float f1 = dp.y + sp.y + (h1.x + h1.y);
        float s0 = dp.z + sp.z + (h2.x + h2.y);
        float s1 = dp.w + sp.w + (h3.x + h3.y);
        float m0 = sigmoid_f(f0) * softplus_f(s0);
        float m1 = sigmoid_f(f1) * softplus_f(s1);

        // pair lanes: even lane issues one v4 RED for 4 consecutive channels
        float m2 = __shfl_down_sync(0xFFFFFFFFu, m0, 1);
        float m3 = __shfl_down_sync(0xFFFFFFFFu, m1, 1);
        if ((lane & 1) == 0) {
            unsigned long long addr = (unsigned long long)(y + (size_t)d * 64 + c0);
            asm volatile("red.global.add.v4.f32 [%0], {%1, %2, %3, %4};"
                         :: "l"(addr), "f"(m0), "f"(m1), "f"(m2), "f"(m3) : "memory");
        }
    }
}

// ---------------- BN stats: fp32 per-block partials ----------------
__global__ __launch_bounds__(256) void stats_kernel(int layer) {
    __shared__ float ssum[256], ssq[256];
    const float* __restrict__ y = layer ? d_y1 : d_y0;
    int t = threadIdx.x;
    int c = t & 63, sub = t >> 6;
    float s = 0.f, q = 0.f;
    for (int r = blockIdx.x * 4 + sub; r < N_NODES; r += NB_STATS * 4) {
        float v = y[(size_t)r * 64 + c];
        s += v;
        q = fmaf(v, v, q);
    }
    ssum[t] = s; ssq[t] = q;
    __syncthreads();
    if (t < 128) { ssum[t] += ssum[t + 128]; ssq[t] += ssq[t + 128]; }
    __syncthreads();
    if (t < 64) {
        d_psum[blockIdx.x * 64 + c] = ssum[t] + ssum[t + 64];
        d_psq[blockIdx.x * 64 + c]  = ssq[t] + ssq[t + 64];
    }
}

__global__ void finalize_stats_kernel(int layer, const float* __restrict__ gamma,
                                      const float* __restrict__ beta) {
    int c = threadIdx.x;
    if (c < 64) {
        double s = 0.0, q = 0.0;
        for (int b = 0; b < NB_STATS; b++) {
            s += (double)d_psum[b * 64 + c];
            q += (double)d_psq[b * 64 + c];
        }
        double m = s / (double)N_NODES;
        double v = q / (double)N_NODES - m * m;
        double sc = (double)gamma[c] * rsqrt(v + 1e-5);
        d_scale[layer][c] = (float)sc;
        d_shift[layer][c] = (float)((double)beta[c] - m * sc);
    }
}

// BN(layer1) fused with global-mean-pool: one block per graph
__global__ __launch_bounds__(256) void pool_kernel(float* __restrict__ out) {
    __shared__ float sred[256];
    int g = blockIdx.x;
    int t = threadIdx.x;
    int c = t & 63, sub = t >> 6;
    int r0 = d_bound[g], r1 = d_bound[g + 1];
    float sc = d_scale[1][c], sh = d_shift[1][c];
    float acc = 0.f;
    for (int r = r0 + sub; r < r1; r += 4)
        acc += d_y1[(size_t)r * 64 + c] * sc + sh;
    sred[t] = acc;
    __syncthreads();
    if (t < 128) sred[t] += sred[t + 128];
    __syncthreads();
    if (t < 64) {
        float total = sred[t] + sred[t + 64];
        float cnt = (float)(r1 - r0);
        out[g * 64 + c] = total / fmaxf(cnt, 1.f);
    }
}

// ---------------- launch ----------------
extern "C" void kernel_launch(void* const* d_in, const int* in_sizes, int n_in,
                              void* d_out, int out_size) {
    const float* x     = (const float*)d_in[0];
    const void*  ei    = d_in[1];
    const float* ea    = (const float*)d_in[2];
    const void*  batch = d_in[3];
    const float *Wf0 = (const float*)d_in[4],  *bf0 = (const float*)d_in[5];
    const float *Ws0 = (const float*)d_in[6],  *bs0 = (const float*)d_in[7];
    const float *g0  = (const float*)d_in[8],  *be0 = (const float*)d_in[9];
    const float *Wf1 = (const float*)d_in[10], *bf1 = (const float*)d_in[11];
    const float *Ws1 = (const float*)d_in[12], *bs1 = (const float*)d_in[13];
    const float *g1  = (const float*)d_in[14], *be1 = (const float*)d_in[15];
    float* out = (float*)d_out;

    const int nodeBlocks = (N_NODES + 63) / 64;   // 782

    detect_bounds_kernel<<<1, 128>>>((const int*)ei, (const int*)batch);
    prep_kernel<<<72, 256>>>(Wf0, Ws0, bf0, bs0, Wf1, Ws1, bf1, bs1);

    // layer 0   (edge_kernel is the 4th launch -> gets profiled)
    node_gemm_kernel<<<nodeBlocks, 256>>>(x, 0);
    edge_kernel<<<NB_EDGE, 256>>>(ei, ea, 0);
    stats_kernel<<<NB_STATS, 256>>>(0);
    finalize_stats_kernel<<<1, 64>>>(0, g0, be0);

    // layer 1 (BN0 folded into node_gemm input + residual init)
    node_gemm_kernel<<<nodeBlocks, 256>>>(x, 1);
    edge_kernel<<<NB_EDGE, 256>>>(ei, ea, 1);
    stats_kernel<<<NB_STATS, 256>>>(1);
    finalize_stats_kernel<<<1, 64>>>(1, g1, be1);

    // pool + output
    pool_kernel<<<64, 256>>>(out);
}

// round 11
// speedup vs baseline: 1.1560x; 1.1560x over previous
#include <cuda_runtime.h>
#include <cuda_bf16.h>
#include <cstdint>

#define N_NODES 50000
#define E_EDGES 800000
#define NB_STATS 240
#define NB_K1   6250   // 800000 / 128 edges per block
#define NB_K2   1036   // 7 blocks/SM * 148 SMs

// ---------------- device scratch (static, no allocs) ----------------
// P layout per node (256 floats):
//   dst [0,128):   channel c -> {fd,sd} at offset 2c   (lane reads float4 at lane*4 = {fd,sd,fd',sd'})
//   src [128,256): channel c -> {fs,ss} at offset 128+2c
__device__ __align__(16) float  d_P[(size_t)N_NODES * 256];
__device__ __align__(16) float  d_Q[(size_t)E_EDGES * 128];   // {qf_c, qs_c} interleaved
__device__ __align__(16) float  d_y0[(size_t)N_NODES * 64];
__device__ __align__(16) float  d_y1[(size_t)N_NODES * 64];
__device__ __align__(16) float  d_Wnode[2][64 * 256];
__device__ __align__(16) float  d_WqG[2][16 * 128];           // [k][2j]=wf, [k][2j+1]=ws
__device__ float  d_bias2[2][256];
__device__ float  d_psum[NB_STATS * 64];
__device__ float  d_psq[NB_STATS * 64];
__device__ __align__(16) float  d_scale[2][64];
__device__ __align__(16) float  d_shift[2][64];
__device__ int    d_bound[65];
__device__ int    d_ei64;

__device__ __forceinline__ float sigmoid_f(float x) {
    float t;
    asm("tanh.approx.f32 %0, %1;" : "=f"(t) : "f"(x * 0.5f));
    return fmaf(0.5f, t, 0.5f);
}
__device__ __forceinline__ float softplus_f(float x) {
    return (x > 20.f) ? x : __logf(1.f + __expf(x));
}
__device__ __forceinline__ uint64_t fma2(uint64_t a, uint64_t b, uint64_t c) {
    uint64_t d;
    asm("fma.rn.f32x2 %0, %1, %2, %3;" : "=l"(d) : "l"(a), "l"(b), "l"(c));
    return d;
}
__device__ __forceinline__ float2 unpack2(uint64_t v) {
    float2 r;
    asm("mov.b64 {%0, %1}, %2;" : "=f"(r.x), "=f"(r.y) : "l"(v));
    return r;
}
__device__ __forceinline__ uint64_t pack2(float a, float b) {
    uint64_t r;
    asm("mov.b64 %0, {%1, %2};" : "=l"(r) : "f"(a), "f"(b));
    return r;
}

// ---------------- dtype detection + graph bounds (1 block) ----------------
__global__ void detect_bounds_kernel(const int* __restrict__ ei32, const int* __restrict__ b32) {
    __shared__ int sb64;
    if (threadIdx.x == 0) {
        int o = 0;
        #pragma unroll
        for (int i = 1; i < 64; i += 2) o |= ei32[i];
        d_ei64 = (o == 0) ? 1 : 0;
        sb64 = (b32[N_NODES - 1] == 0) ? 1 : 0;
    }
    __syncthreads();
    int g = threadIdx.x;
    if (g <= 64) {
        int b64 = sb64;
        const long long* bL = (const long long*)b32;
        int lo = 0, hi = N_NODES;
        while (lo < hi) {
            int mid = (lo + hi) >> 1;
            long long bv = b64 ? bL[mid] : (long long)b32[mid];
            if (bv < (long long)g) lo = mid + 1; else hi = mid;
        }
        d_bound[g] = lo;
    }
}

// ---------------- prep: pack weights ----------------
__global__ void prep_kernel(const float* __restrict__ Wf0, const float* __restrict__ Ws0,
                            const float* __restrict__ bf0, const float* __restrict__ bs0,
                            const float* __restrict__ Wf1, const float* __restrict__ Ws1,
                            const float* __restrict__ bf1, const float* __restrict__ bs1) {
    int stride = gridDim.x * blockDim.x;
    int gid = blockIdx.x * blockDim.x + threadIdx.x;
    for (int i = gid; i < 2 * 64 * 144; i += stride) {
        int l = i / 9216; int r = i % 9216; int j = r / 144; int k = r % 144;
        const float* Wf = l ? Wf1 : Wf0;
        const float* Ws = l ? Ws1 : Ws0;
        float wf = Wf[j * 144 + k], ws = Ws[j * 144 + k];
        if (k < 64) {
            d_Wnode[l][k * 256 + 2 * j]     = wf;
            d_Wnode[l][k * 256 + 2 * j + 1] = ws;
        } else if (k < 128) {
            int kk = k - 64;
            d_Wnode[l][kk * 256 + 128 + 2 * j]     = wf;
            d_Wnode[l][kk * 256 + 128 + 2 * j + 1] = ws;
        } else {
            int kk = k - 128;
            d_WqG[l][kk * 128 + 2 * j]     = wf;
            d_WqG[l][kk * 128 + 2 * j + 1] = ws;
        }
    }
    for (int i = gid; i < 2 * 64; i += stride) {
        int l = i >> 6; int j = i & 63;
        const float* bf = l ? bf1 : bf0;
        const float* bs = l ? bs1 : bs0;
        d_bias2[l][2 * j]           = bf[j];
        d_bias2[l][2 * j + 1]       = bs[j];
        d_bias2[l][128 + 2 * j]     = 0.f;
        d_bias2[l][128 + 2 * j + 1] = 0.f;
    }
}

// ---------------- node GEMM: P = in @ Wnode + bias; writes residual into y ----------------
__global__ __launch_bounds__(256, 2) void node_gemm_kernel(const float* __restrict__ x_in, int layer) {
    __shared__ __align__(16) float sX[64 * 68];
    __shared__ float sB[256];
    __shared__ float sSc[64], sSh[64];
    int t = threadIdx.x;
    int n0 = blockIdx.x * 64;
    const float* __restrict__ src = layer ? d_y0 : x_in;
    float* __restrict__ y = layer ? d_y1 : d_y0;
    const float* __restrict__ Wn = d_Wnode[layer];

    sB[t] = d_bias2[layer][t];
    if (t < 64) {
        sSc[t] = layer ? d_scale[0][t] : 1.f;
        sSh[t] = layer ? d_shift[0][t] : 0.f;
    }
    __syncthreads();
    {
        int n = t >> 2, q = t & 3;
        int node = n0 + n;
        #pragma unroll
        for (int i = 0; i < 4; i++) {
            int k = q * 16 + i * 4;
            float4 v = make_float4(0.f, 0.f, 0.f, 0.f);
            if (node < N_NODES) v = *(const float4*)&src[(size_t)node * 64 + k];
            float4 w = make_float4(v.x * sSc[k + 0] + sSh[k + 0],
                                   v.y * sSc[k + 1] + sSh[k + 1],
                                   v.z * sSc[k + 2] + sSh[k + 2],
                                   v.w * sSc[k + 3] + sSh[k + 3]);
            sX[(k + 0) * 68 + n] = w.x;
            sX[(k + 1) * 68 + n] = w.y;
            sX[(k + 2) * 68 + n] = w.z;
            sX[(k + 3) * 68 + n] = w.w;
            if (node < N_NODES) *(float4*)&y[(size_t)node * 64 + k] = w;  // residual init
        }
    }
    __syncthreads();

    int tx = t & 31, ty = t >> 5;
    float acc[8][8];
    #pragma unroll
    for (int e = 0; e < 8; e++)
        #pragma unroll
        for (int j = 0; j < 8; j++) acc[e][j] = 0.f;

    #pragma unroll 8
    for (int k = 0; k < 64; k++) {
        float4 w0 = *(const float4*)&Wn[k * 256 + tx * 8];
        float4 w1 = *(const float4*)&Wn[k * 256 + tx * 8 + 4];
        float4 z0 = *(const float4*)&sX[k * 68 + ty * 8];
        float4 z1 = *(const float4*)&sX[k * 68 + ty * 8 + 4];
        float ww[8] = {w0.x, w0.y, w0.z, w0.w, w1.x, w1.y, w1.z, w1.w};
        float zz[8] = {z0.x, z0.y, z0.z, z0.w, z1.x, z1.y, z1.z, z1.w};
        #pragma unroll
        for (int e = 0; e < 8; e++)
            #pragma unroll
            for (int j = 0; j < 8; j++) acc[e][j] += zz[e] * ww[j];
    }

    float b[8];
    #pragma unroll
    for (int j = 0; j < 8; j++) b[j] = sB[tx * 8 + j];
    #pragma unroll
    for (int e = 0; e < 8; e++) {
        int node = n0 + ty * 8 + e;
        if (node < N_NODES) {
            float4 o0 = make_float4(acc[e][0] + b[0], acc[e][1] + b[1], acc[e][2] + b[2], acc[e][3] + b[3]);
            float4 o1 = make_float4(acc[e][4] + b[4], acc[e][5] + b[5], acc[e][6] + b[6], acc[e][7] + b[7]);
            *(float4*)&d_P[(size_t)node * 256 + tx * 8]     = o0;
            *(float4*)&d_P[(size_t)node * 256 + tx * 8 + 4] = o1;
        }
    }
}

// ---------------- K1: edge GEMM  Q[e][128] = ea[e][16] @ WqG  (128 edges/block) ----------------
__global__ __launch_bounds__(256) void edge_gemm_kernel(const float* __restrict__ ea, int layer) {
    __shared__ __align__(16) float sEa[16][132];      // [k][edge]
    __shared__ __align__(16) float sW[16 * 128];      // [k][out]
    int t = threadIdx.x;
    int e0 = blockIdx.x * 128;
    const float* __restrict__ W = d_WqG[layer];

    // load weights (2048 floats)
    #pragma unroll
    for (int i = 0; i < 2; i++) {
        int idx = t + i * 256;                         // float4 index, 512 total
        *(float4*)&sW[idx * 4] = *(const float4*)&W[idx * 4];
    }
    // load + transpose ea tile: 128 edges x 16 floats = 512 float4s
    #pragma unroll
    for (int i = 0; i < 2; i++) {
        int idx = t + i * 256;
        int e = idx >> 2, q = idx & 3;
        float4 v = *(const float4*)&ea[(size_t)(e0 + e) * 16 + q * 4];
        sEa[4 * q + 0][e] = v.x;
        sEa[4 * q + 1][e] = v.y;
        sEa[4 * q + 2][e] = v.z;
        sEa[4 * q + 3][e] = v.w;
    }
    __syncthreads();

    int o = (t & 15) * 8;        // 8 outputs = 4 f32x2 pairs
    int g = (t >> 4) * 8;        // 8 edges
    uint64_t acc[8][4];
    #pragma unroll
    for (int e = 0; e < 8; e++)
        #pragma unroll
        for (int p = 0; p < 4; p++) acc[e][p] = 0;

    #pragma unroll
    for (int k = 0; k < 16; k++) {
        const ulonglong2* wp = (const ulonglong2*)&sW[k * 128 + o];
        ulonglong2 w01 = wp[0], w23 = wp[1];
        #pragma unroll
        for (int e = 0; e < 8; e++) {
            float a = sEa[k][g + e];
            uint64_t aa = pack2(a, a);
            acc[e][0] = fma2(aa, w01.x, acc[e][0]);
            acc[e][1] = fma2(aa, w01.y, acc[e][1]);
            acc[e][2] = fma2(aa, w23.x, acc[e][2]);
            acc[e][3] = fma2(aa, w23.y, acc[e][3]);
        }
    }

    #pragma unroll
    for (int e = 0; e < 8; e++) {
        float2 a0 = unpack2(acc[e][0]), a1 = unpack2(acc[e][1]);
        float2 a2 = unpack2(acc[e][2]), a3 = unpack2(acc[e][3]);
        float* Qd = &d_Q[(size_t)(e0 + g + e) * 128 + o];
        *(float4*)&Qd[0] = make_float4(a0.x, a0.y, a1.x, a1.y);
        *(float4*)&Qd[4] = make_float4(a2.x, a2.y, a3.x, a3.y);
    }
}

// ---------------- K2: edge apply — warp = 1 edge, lane = 2 channels, v4 RED ----------------
__global__ __launch_bounds__(256) void edge_apply_kernel(const void* __restrict__ ei_raw, int layer) {
    float* __restrict__ y = layer ? d_y1 : d_y0;
    int tid = threadIdx.x, warp = tid >> 5, lane = tid & 31;
    int gw = blockIdx.x * 8 + warp;
    const int nw = NB_K2 * 8;
    const int ei64 = d_ei64;
    const long long* eL = (const long long*)ei_raw;
    const int*       eI = (const int*)ei_raw;

    for (int e = gw; e < E_EDGES; e += nw) {
        int s, d;
        if (ei64) { s = (int)eL[e]; d = (int)eL[E_EDGES + e]; }
        else      { s = eI[e];      d = eI[E_EDGES + e]; }
        s = min(max(s, 0), N_NODES - 1);
        d = min(max(d, 0), N_NODES - 1);

        float4 dp = *(const float4*)&d_P[(size_t)d * 256 + lane * 4];        // {fd_a,sd_a,fd_b,sd_b}
        float4 sp = *(const float4*)&d_P[(size_t)s * 256 + 128 + lane * 4];  // {fs_a,ss_a,fs_b,ss_b}
        float4 q  = *(const float4*)&d_Q[(size_t)e * 128 + lane * 4];        // {qf_a,qs_a,qf_b,qs_b}

        float fa = dp.x + sp.x + q.x;
        float sa = dp.y + sp.y + q.y;
        float fb = dp.z + sp.z + q.z;
        float sb = dp.w + sp.w + q.w;
        float ma = sigmoid_f(fa) * softplus_f(sa);
        float mb = sigmoid_f(fb) * softplus_f(sb);

        float m2 = __shfl_down_sync(0xFFFFFFFFu, ma, 1);
        float m3 = __shfl_down_sync(0xFFFFFFFFu, mb, 1);
        if ((lane & 1) == 0) {
            unsigned long long addr = (unsigned long long)(y + (size_t)d * 64 + lane * 2);
            asm volatile("red.global.add.v4.f32 [%0], {%1, %2, %3, %4};"
                         :: "l"(addr), "f"(ma), "f"(mb), "f"(m2), "f"(m3) : "memory");
        }
    }
}

// ---------------- BN stats: fp32 per-block partials ----------------
__global__ __launch_bounds__(256) void stats_kernel(int layer) {
    __shared__ float ssum[256], ssq[256];
    const float* __restrict__ y = layer ? d_y1 : d_y0;
    int t = threadIdx.x;
    int c = t & 63, sub = t >> 6;
    float s = 0.f, q = 0.f;
    for (int r = blockIdx.x * 4 + sub; r < N_NODES; r += NB_STATS * 4) {
        float v = y[(size_t)r * 64 + c];
        s += v;
        q = fmaf(v, v, q);
    }
    ssum[t] = s; ssq[t] = q;
    __syncthreads();
    if (t < 128) { ssum[t] += ssum[t + 128]; ssq[t] += ssq[t + 128]; }
    __syncthreads();
    if (t < 64) {
        d_psum[blockIdx.x * 64 + c] = ssum[t] + ssum[t + 64];
        d_psq[blockIdx.x * 64 + c]  = ssq[t] + ssq[t + 64];
    }
}

__global__ void finalize_stats_kernel(int layer, const float* __restrict__ gamma,
                                      const float* __restrict__ beta) {
    int c = threadIdx.x;
    if (c < 64) {
        double s = 0.0, q = 0.0;
        for (int b = 0; b < NB_STATS; b++) {
            s += (double)d_psum[b * 64 + c];
            q += (double)d_psq[b * 64 + c];
        }
        double m = s / (double)N_NODES;
        double v = q / (double)N_NODES - m * m;
        double sc = (double)gamma[c] * rsqrt(v + 1e-5);
        d_scale[layer][c] = (float)sc;
        d_shift[layer][c] = (float)((double)beta[c] - m * sc);
    }
}

// BN(layer1) fused with global-mean-pool: one block per graph
__global__ __launch_bounds__(256) void pool_kernel(float* __restrict__ out) {
    __shared__ float sred[256];
    int g = blockIdx.x;
    int t = threadIdx.x;
    int c = t & 63, sub = t >> 6;
    int r0 = d_bound[g], r1 = d_bound[g + 1];
    float sc = d_scale[1][c], sh = d_shift[1][c];
    float acc = 0.f;
    for (int r = r0 + sub; r < r1; r += 4)
        acc += d_y1[(size_t)r * 64 + c] * sc + sh;
    sred[t] = acc;
    __syncthreads();
    if (t < 128) sred[t] += sred[t + 128];
    __syncthreads();
    if (t < 64) {
        float total = sred[t] + sred[t + 64];
        float cnt = (float)(r1 - r0);
        out[g * 64 + c] = total / fmaxf(cnt, 1.f);
    }
}

// ---------------- launch ----------------
extern "C" void kernel_launch(void* const* d_in, const int* in_sizes, int n_in,
                              void* d_out, int out_size) {
    const float* x     = (const float*)d_in[0];
    const void*  ei    = d_in[1];
    const float* ea    = (const float*)d_in[2];
    const void*  batch = d_in[3];
    const float *Wf0 = (const float*)d_in[4],  *bf0 = (const float*)d_in[5];
    const float *Ws0 = (const float*)d_in[6],  *bs0 = (const float*)d_in[7];
    const float *g0  = (const float*)d_in[8],  *be0 = (const float*)d_in[9];
    const float *Wf1 = (const float*)d_in[10], *bf1 = (const float*)d_in[11];
    const float *Ws1 = (const float*)d_in[12], *bs1 = (const float*)d_in[13];
    const float *g1  = (const float*)d_in[14], *be1 = (const float*)d_in[15];
    float* out = (float*)d_out;

    const int nodeBlocks = (N_NODES + 63) / 64;   // 782

    detect_bounds_kernel<<<1, 128>>>((const int*)ei, (const int*)batch);
    prep_kernel<<<72, 256>>>(Wf0, Ws0, bf0, bs0, Wf1, Ws1, bf1, bs1);

    // layer 0
    node_gemm_kernel<<<nodeBlocks, 256>>>(x, 0);
    edge_gemm_kernel<<<NB_K1, 256>>>(ea, 0);
    edge_apply_kernel<<<NB_K2, 256>>>(ei, 0);
    stats_kernel<<<NB_STATS, 256>>>(0);
    finalize_stats_kernel<<<1, 64>>>(0, g0, be0);

    // layer 1 (BN0 folded into node_gemm input + residual init)
    node_gemm_kernel<<<nodeBlocks, 256>>>(x, 1);
    edge_gemm_kernel<<<NB_K1, 256>>>(ea, 1);
    edge_apply_kernel<<<NB_K2, 256>>>(ei, 1);
    stats_kernel<<<NB_STATS, 256>>>(1);
    finalize_stats_kernel<<<1, 64>>>(1, g1, be1);

    // pool + output
    pool_kernel<<<64, 256>>>(out);
}

// round 12
// speedup vs baseline: 1.1654x; 1.0082x over previous
#include <cuda_runtime.h>
#include <cuda_bf16.h>
#include <cstdint>

#define N_NODES 50000
#define E_EDGES 800000
#define NB_STATS 240
#define NB_K1   6250   // 800000 / 128 edges per block
#define NB_K2   1036   // 7 blocks/SM * 148 SMs

// ---------------- device scratch (static, no allocs) ----------------
// P layout per node (256 floats):
//   dst [0,128):   channel c -> {fd,sd} at offset 2c   (lane reads float4 at lane*4 = {fd,sd,fd',sd'})
//   src [128,256): channel c -> {fs,ss} at offset 128+2c
__device__ __align__(16) float  d_P[(size_t)N_NODES * 256];
__device__ __align__(16) float  d_Q[(size_t)E_EDGES * 128];   // {qf_c, qs_c} interleaved
__device__ __align__(16) float  d_y0[(size_t)N_NODES * 64];
__device__ __align__(16) float  d_y1[(size_t)N_NODES * 64];
__device__ __align__(16) float  d_Wnode[2][64 * 256];
__device__ __align__(16) float  d_WqG[2][16 * 128];           // [k][2j]=wf, [k][2j+1]=ws
__device__ float  d_bias2[2][256];
__device__ float  d_psum[NB_STATS * 64];
__device__ float  d_psq[NB_STATS * 64];
__device__ __align__(16) float  d_scale[2][64];
__device__ __align__(16) float  d_shift[2][64];
__device__ int    d_bound[65];
__device__ int    d_ei64;

__device__ __forceinline__ float sigmoid_f(float x) {
    float t;
    asm("tanh.approx.f32 %0, %1;" : "=f"(t) : "f"(x * 0.5f));
    return fmaf(0.5f, t, 0.5f);
}
__device__ __forceinline__ float softplus_f(float x) {
    return (x > 20.f) ? x : __logf(1.f + __expf(x));
}
__device__ __forceinline__ uint64_t fma2(uint64_t a, uint64_t b, uint64_t c) {
    uint64_t d;
    asm("fma.rn.f32x2 %0, %1, %2, %3;" : "=l"(d) : "l"(a), "l"(b), "l"(c));
    return d;
}
__device__ __forceinline__ float2 unpack2(uint64_t v) {
    float2 r;
    asm("mov.b64 {%0, %1}, %2;" : "=f"(r.x), "=f"(r.y) : "l"(v));
    return r;
}
__device__ __forceinline__ uint64_t pack2(float a, float b) {
    uint64_t r;
    asm("mov.b64 %0, {%1, %2};" : "=l"(r) : "f"(a), "f"(b));
    return r;
}

// ---------------- dtype detection + graph bounds (1 block) ----------------
__global__ void detect_bounds_kernel(const int* __restrict__ ei32, const int* __restrict__ b32) {
    __shared__ int sb64;
    if (threadIdx.x == 0) {
        int o = 0;
        #pragma unroll
        for (int i = 1; i < 64; i += 2) o |= ei32[i];
        d_ei64 = (o == 0) ? 1 : 0;
        sb64 = (b32[N_NODES - 1] == 0) ? 1 : 0;
    }
    __syncthreads();
    int g = threadIdx.x;
    if (g <= 64) {
        int b64 = sb64;
        const long long* bL = (const long long*)b32;
        int lo = 0, hi = N_NODES;
        while (lo < hi) {
            int mid = (lo + hi) >> 1;
            long long bv = b64 ? bL[mid] : (long long)b32[mid];
            if (bv < (long long)g) lo = mid + 1; else hi = mid;
        }
        d_bound[g] = lo;
    }
}

// ---------------- prep: pack weights ----------------
__global__ void prep_kernel(const float* __restrict__ Wf0, const float* __restrict__ Ws0,
                            const float* __restrict__ bf0, const float* __restrict__ bs0,
                            const float* __restrict__ Wf1, const float* __restrict__ Ws1,
                            const float* __restrict__ bf1, const float* __restrict__ bs1) {
    int stride = gridDim.x * blockDim.x;
    int gid = blockIdx.x * blockDim.x + threadIdx.x;
    for (int i = gid; i < 2 * 64 * 144; i += stride) {
        int l = i / 9216; int r = i % 9216; int j = r / 144; int k = r % 144;
        const float* Wf = l ? Wf1 : Wf0;
        const float* Ws = l ? Ws1 : Ws0;
        float wf = Wf[j * 144 + k], ws = Ws[j * 144 + k];
        if (k < 64) {
            d_Wnode[l][k * 256 + 2 * j]     = wf;
            d_Wnode[l][k * 256 + 2 * j + 1] = ws;
        } else if (k < 128) {
            int kk = k - 64;
            d_Wnode[l][kk * 256 + 128 + 2 * j]     = wf;
            d_Wnode[l][kk * 256 + 128 + 2 * j + 1] = ws;
        } else {
            int kk = k - 128;
            d_WqG[l][kk * 128 + 2 * j]     = wf;
            d_WqG[l][kk * 128 + 2 * j + 1] = ws;
        }
    }
    for (int i = gid; i < 2 * 64; i += stride) {
        int l = i >> 6; int j = i & 63;
        const float* bf = l ? bf1 : bf0;
        const float* bs = l ? bs1 : bs0;
        d_bias2[l][2 * j]           = bf[j];
        d_bias2[l][2 * j + 1]       = bs[j];
        d_bias2[l][128 + 2 * j]     = 0.f;
        d_bias2[l][128 + 2 * j + 1] = 0.f;
    }
}

// ---------------- node GEMM: P = in @ Wnode + bias; writes residual into y ----------------
__global__ __launch_bounds__(256, 2) void node_gemm_kernel(const float* __restrict__ x_in, int layer) {
    __shared__ __align__(16) float sX[64 * 68];
    __shared__ float sB[256];
    __shared__ float sSc[64], sSh[64];
    int t = threadIdx.x;
    int n0 = blockIdx.x * 64;
    const float* __restrict__ src = layer ? d_y0 : x_in;
    float* __restrict__ y = layer ? d_y1 : d_y0;
    const float* __restrict__ Wn = d_Wnode[layer];

    sB[t] = d_bias2[layer][t];
    if (t < 64) {
        sSc[t] = layer ? d_scale[0][t] : 1.f;
        sSh[t] = layer ? d_shift[0][t] : 0.f;
    }
    __syncthreads();
    {
        int n = t >> 2, q = t & 3;
        int node = n0 + n;
        #pragma unroll
        for (int i = 0; i < 4; i++) {
            int k = q * 16 + i * 4;
            float4 v = make_float4(0.f, 0.f, 0.f, 0.f);
            if (node < N_NODES) v = *(const float4*)&src[(size_t)node * 64 + k];
            float4 w = make_float4(v.x * sSc[k + 0] + sSh[k + 0],
                                   v.y * sSc[k + 1] + sSh[k + 1],
                                   v.z * sSc[k + 2] + sSh[k + 2],
                                   v.w * sSc[k + 3] + sSh[k + 3]);
            sX[(k + 0) * 68 + n] = w.x;
            sX[(k + 1) * 68 + n] = w.y;
            sX[(k + 2) * 68 + n] = w.z;
            sX[(k + 3) * 68 + n] = w.w;
            if (node < N_NODES) *(float4*)&y[(size_t)node * 64 + k] = w;  // residual init
        }
    }
    __syncthreads();

    int tx = t & 31, ty = t >> 5;
    float acc[8][8];
    #pragma unroll
    for (int e = 0; e < 8; e++)
        #pragma unroll
        for (int j = 0; j < 8; j++) acc[e][j] = 0.f;

    #pragma unroll 8
    for (int k = 0; k < 64; k++) {
        float4 w0 = *(const float4*)&Wn[k * 256 + tx * 8];
        float4 w1 = *(const float4*)&Wn[k * 256 + tx * 8 + 4];
        float4 z0 = *(const float4*)&sX[k * 68 + ty * 8];
        float4 z1 = *(const float4*)&sX[k * 68 + ty * 8 + 4];
        float ww[8] = {w0.x, w0.y, w0.z, w0.w, w1.x, w1.y, w1.z, w1.w};
        float zz[8] = {z0.x, z0.y, z0.z, z0.w, z1.x, z1.y, z1.z, z1.w};
        #pragma unroll
        for (int e = 0; e < 8; e++)
            #pragma unroll
            for (int j = 0; j < 8; j++) acc[e][j] += zz[e] * ww[j];
    }

    float b[8];
    #pragma unroll
    for (int j = 0; j < 8; j++) b[j] = sB[tx * 8 + j];
    #pragma unroll
    for (int e = 0; e < 8; e++) {
        int node = n0 + ty * 8 + e;
        if (node < N_NODES) {
            float4 o0 = make_float4(acc[e][0] + b[0], acc[e][1] + b[1], acc[e][2] + b[2], acc[e][3] + b[3]);
            float4 o1 = make_float4(acc[e][4] + b[4], acc[e][5] + b[5], acc[e][6] + b[6], acc[e][7] + b[7]);
            *(float4*)&d_P[(size_t)node * 256 + tx * 8]     = o0;
            *(float4*)&d_P[(size_t)node * 256 + tx * 8 + 4] = o1;
        }
    }
}

// ---------------- K1: edge GEMM  Q[e][128] = ea[e][16] @ WqG  (128 edges/block) ----------------
__global__ __launch_bounds__(256) void edge_gemm_kernel(const float* __restrict__ ea, int layer) {
    __shared__ __align__(16) float sEa[16][132];      // [k][edge]
    __shared__ __align__(16) float sW[16 * 128];      // [k][out]
    int t = threadIdx.x;
    int e0 = blockIdx.x * 128;
    const float* __restrict__ W = d_WqG[layer];

    // load weights (2048 floats)
    #pragma unroll
    for (int i = 0; i < 2; i++) {
        int idx = t + i * 256;                         // float4 index, 512 total
        *(float4*)&sW[idx * 4] = *(const float4*)&W[idx * 4];
    }
    // load + transpose ea tile: 128 edges x 16 floats = 512 float4s
    #pragma unroll
    for (int i = 0; i < 2; i++) {
        int idx = t + i * 256;
        int e = idx >> 2, q = idx & 3;
        float4 v = *(const float4*)&ea[(size_t)(e0 + e) * 16 + q * 4];
        sEa[4 * q + 0][e] = v.x;
        sEa[4 * q + 1][e] = v.y;
        sEa[4 * q + 2][e] = v.z;
        sEa[4 * q + 3][e] = v.w;
    }
    __syncthreads();

    int o = (t & 15) * 8;        // 8 outputs = 4 f32x2 pairs
    int g = (t >> 4) * 8;        // 8 edges
    uint64_t acc[8][4];
    #pragma unroll
    for (int e = 0; e < 8; e++)
        #pragma unroll
        for (int p = 0; p < 4; p++) acc[e][p] = 0;

    #pragma unroll
    for (int k = 0; k < 16; k++) {
        const ulonglong2* wp = (const ulonglong2*)&sW[k * 128 + o];
        ulonglong2 w01 = wp[0], w23 = wp[1];
        #pragma unroll
        for (int e = 0; e < 8; e++) {
            float a = sEa[k][g + e];
            uint64_t aa = pack2(a, a);
            acc[e][0] = fma2(aa, w01.x, acc[e][0]);
            acc[e][1] = fma2(aa, w01.y, acc[e][1]);
            acc[e][2] = fma2(aa, w23.x, acc[e][2]);
            acc[e][3] = fma2(aa, w23.y, acc[e][3]);
        }
    }

    #pragma unroll
    for (int e = 0; e < 8; e++) {
        float2 a0 = unpack2(acc[e][0]), a1 = unpack2(acc[e][1]);
        float2 a2 = unpack2(acc[e][2]), a3 = unpack2(acc[e][3]);
        float* Qd = &d_Q[(size_t)(e0 + g + e) * 128 + o];
        *(float4*)&Qd[0] = make_float4(a0.x, a0.y, a1.x, a1.y);
        *(float4*)&Qd[4] = make_float4(a2.x, a2.y, a3.x, a3.y);
    }
}

// ---------------- K2: edge apply — warp = 1 edge, lane = 2 channels, v4 RED ----------------
__global__ __launch_bounds__(256) void edge_apply_kernel(const void* __restrict__ ei_raw, int layer) {
    float* __restrict__ y = layer ? d_y1 : d_y0;
    int tid = threadIdx.x, warp = tid >> 5, lane = tid & 31;
    int gw = blockIdx.x * 8 + warp;
    const int nw = NB_K2 * 8;
    const int ei64 = d_ei64;
    const long long* eL = (const long long*)ei_raw;
    const int*       eI = (const int*)ei_raw;

    for (int e = gw; e < E_EDGES; e += nw) {
        int s, d;
        if (ei64) { s = (int)eL[e]; d = (int)eL[E_EDGES + e]; }
        else      { s = eI[e];      d = eI[E_EDGES + e]; }
        s = min(max(s, 0), N_NODES - 1);
        d = min(max(d, 0), N_NODES - 1);

        float4 dp = *(const float4*)&d_P[(size_t)d * 256 + lane * 4];        // {fd_a,sd_a,fd_b,sd_b}
        float4 sp = *(const float4*)&d_P[(size_t)s * 256 + 128 + lane * 4];  // {fs_a,ss_a,fs_b,ss_b}
        float4 q  = *(const float4*)&d_Q[(size_t)e * 128 + lane * 4];        // {qf_a,qs_a,qf_b,qs_b}

        float fa = dp.x + sp.x + q.x;
        float sa = dp.y + sp.y + q.y;
        float fb = dp.z + sp.z + q.z;
        float sb = dp.w + sp.w + q.w;
        float ma = sigmoid_f(fa) * softplus_f(sa);
        float mb = sigmoid_f(fb) * softplus_f(sb);

        float m2 = __shfl_down_sync(0xFFFFFFFFu, ma, 1);
        float m3 = __shfl_down_sync(0xFFFFFFFFu, mb, 1);
        if ((lane & 1) == 0) {
            unsigned long long addr = (unsigned long long)(y + (size_t)d * 64 + lane * 2);
            asm volatile("red.global.add.v4.f32 [%0], {%1, %2, %3, %4};"
                         :: "l"(addr), "f"(ma), "f"(mb), "f"(m2), "f"(m3) : "memory");
        }
    }
}

// ---------------- BN stats: fp32 per-block partials ----------------
__global__ __launch_bounds__(256) void stats_kernel(int layer) {
    __shared__ float ssum[256], ssq[256];
    const float* __restrict__ y = layer ? d_y1 : d_y0;
    int t = threadIdx.x;
    int c = t & 63, sub = t >> 6;
    float s = 0.f, q = 0.f;
    for (int r = blockIdx.x * 4 + sub; r < N_NODES; r += NB_STATS * 4) {
        float v = y[(size_t)r * 64 + c];
        s += v;
        q = fmaf(v, v, q);
    }
    ssum[t] = s; ssq[t] = q;
    __syncthreads();
    if (t < 128) { ssum[t] += ssum[t + 128]; ssq[t] += ssq[t + 128]; }
    __syncthreads();
    if (t < 64) {
        d_psum[blockIdx.x * 64 + c] = ssum[t] + ssum[t + 64];
        d_psq[blockIdx.x * 64 + c]  = ssq[t] + ssq[t + 64];
    }
}

__global__ void finalize_stats_kernel(int layer, const float* __restrict__ gamma,
                                      const float* __restrict__ beta) {
    int c = threadIdx.x;
    if (c < 64) {
        double s = 0.0, q = 0.0;
        for (int b = 0; b < NB_STATS; b++) {
            s += (double)d_psum[b * 64 + c];
            q += (double)d_psq[b * 64 + c];
        }
        double m = s / (double)N_NODES;
        double v = q / (double)N_NODES - m * m;
        double sc = (double)gamma[c] * rsqrt(v + 1e-5);
        d_scale[layer][c] = (float)sc;
        d_shift[layer][c] = (float)((double)beta[c] - m * sc);
    }
}

// BN(layer1) fused with global-mean-pool: one block per graph
__global__ __launch_bounds__(256) void pool_kernel(float* __restrict__ out) {
    __shared__ float sred[256];
    int g = blockIdx.x;
    int t = threadIdx.x;
    int c = t & 63, sub = t >> 6;
    int r0 = d_bound[g], r1 = d_bound[g + 1];
    float sc = d_scale[1][c], sh = d_shift[1][c];
    float acc = 0.f;
    for (int r = r0 + sub; r < r1; r += 4)
        acc += d_y1[(size_t)r * 64 + c] * sc + sh;
    sred[t] = acc;
    __syncthreads();
    if (t < 128) sred[t] += sred[t + 128];
    __syncthreads();
    if (t < 64) {
        float total = sred[t] + sred[t + 64];
        float cnt = (float)(r1 - r0);
        out[g * 64 + c] = total / fmaxf(cnt, 1.f);
    }
}

// ---------------- launch ----------------
extern "C" void kernel_launch(void* const* d_in, const int* in_sizes, int n_in,
                              void* d_out, int out_size) {
    const float* x     = (const float*)d_in[0];
    const void*  ei    = d_in[1];
    const float* ea    = (const float*)d_in[2];
    const void*  batch = d_in[3];
    const float *Wf0 = (const float*)d_in[4],  *bf0 = (const float*)d_in[5];
    const float *Ws0 = (const float*)d_in[6],  *bs0 = (const float*)d_in[7];
    const float *g0  = (const float*)d_in[8],  *be0 = (const float*)d_in[9];
    const float *Wf1 = (const float*)d_in[10], *bf1 = (const float*)d_in[11];
    const float *Ws1 = (const float*)d_in[12], *bs1 = (const float*)d_in[13];
    const float *g1  = (const float*)d_in[14], *be1 = (const float*)d_in[15];
    float* out = (float*)d_out;

    const int nodeBlocks = (N_NODES + 63) / 64;   // 782

    detect_bounds_kernel<<<1, 128>>>((const int*)ei, (const int*)batch);
    prep_kernel<<<72, 256>>>(Wf0, Ws0, bf0, bs0, Wf1, Ws1, bf1, bs1);

    // layer 0
    node_gemm_kernel<<<nodeBlocks, 256>>>(x, 0);
    edge_gemm_kernel<<<NB_K1, 256>>>(ea, 0);
    edge_apply_kernel<<<NB_K2, 256>>>(ei, 0);
    stats_kernel<<<NB_STATS, 256>>>(0);
    finalize_stats_kernel<<<1, 64>>>(0, g0, be0);

    // layer 1 (BN0 folded into node_gemm input + residual init)
    node_gemm_kernel<<<nodeBlocks, 256>>>(x, 1);
    edge_gemm_kernel<<<NB_K1, 256>>>(ea, 1);
    edge_apply_kernel<<<NB_K2, 256>>>(ei, 1);
    stats_kernel<<<NB_STATS, 256>>>(1);
    finalize_stats_kernel<<<1, 64>>>(1, g1, be1);

    // pool + output
    pool_kernel<<<64, 256>>>(out);
}

// round 13
// speedup vs baseline: 1.2886x; 1.1057x over previous
#include <cuda_runtime.h>
#include <cuda_bf16.h>
#include <cstdint>

#define N_NODES 50000
#define E_EDGES 800000
#define NB_STATS 240
#define NB_FUSED 12500   // 800000 / 64 edges per block

// ---------------- device scratch (static, no allocs) ----------------
// P layout per node (256 floats):
//   dst [0,128):   channel c -> {fd,sd} at offset 2c   (lane float4 at lane*4 = {fd_a,sd_a,fd_b,sd_b})
//   src [128,256): channel c -> {fs,ss} at offset 128+2c
__device__ __align__(16) float  d_P[(size_t)N_NODES * 256];
__device__ __align__(16) float  d_y0[(size_t)N_NODES * 64];
__device__ __align__(16) float  d_y1[(size_t)N_NODES * 64];
__device__ __align__(16) float  d_Wnode[2][64 * 256];
__device__ __align__(16) float  d_WqG[2][16 * 128];           // [k][2j]=wf, [k][2j+1]=ws
__device__ float  d_bias2[2][256];
__device__ float  d_psum[NB_STATS * 64];
__device__ float  d_psq[NB_STATS * 64];
__device__ __align__(16) float  d_scale[2][64];
__device__ __align__(16) float  d_shift[2][64];
__device__ int    d_bound[65];
__device__ int    d_ei64;

__device__ __forceinline__ float sigmoid_f(float x) {
    float t;
    asm("tanh.approx.f32 %0, %1;" : "=f"(t) : "f"(x * 0.5f));
    return fmaf(0.5f, t, 0.5f);
}
__device__ __forceinline__ float softplus_f(float x) {
    return (x > 20.f) ? x : __logf(1.f + __expf(x));
}
__device__ __forceinline__ uint64_t fma2(uint64_t a, uint64_t b, uint64_t c) {
    uint64_t d;
    asm("fma.rn.f32x2 %0, %1, %2, %3;" : "=l"(d) : "l"(a), "l"(b), "l"(c));
    return d;
}
__device__ __forceinline__ float2 unpack2(uint64_t v) {
    float2 r;
    asm("mov.b64 {%0, %1}, %2;" : "=f"(r.x), "=f"(r.y) : "l"(v));
    return r;
}
__device__ __forceinline__ uint64_t pack2(float a, float b) {
    uint64_t r;
    asm("mov.b64 %0, {%1, %2};" : "=l"(r) : "f"(a), "f"(b));
    return r;
}

// ---------------- dtype detection + graph bounds (1 block) ----------------
__global__ void detect_bounds_kernel(const int* __restrict__ ei32, const int* __restrict__ b32) {
    __shared__ int sb64;
    if (threadIdx.x == 0) {
        int o = 0;
        #pragma unroll
        for (int i = 1; i < 64; i += 2) o |= ei32[i];
        d_ei64 = (o == 0) ? 1 : 0;
        sb64 = (b32[N_NODES - 1] == 0) ? 1 : 0;
    }
    __syncthreads();
    int g = threadIdx.x;
    if (g <= 64) {
        int b64 = sb64;
        const long long* bL = (const long long*)b32;
        int lo = 0, hi = N_NODES;
        while (lo < hi) {
            int mid = (lo + hi) >> 1;
            long long bv = b64 ? bL[mid] : (long long)b32[mid];
            if (bv < (long long)g) lo = mid + 1; else hi = mid;
        }
        d_bound[g] = lo;
    }
}

// ---------------- prep: pack weights ----------------
__global__ void prep_kernel(const float* __restrict__ Wf0, const float* __restrict__ Ws0,
                            const float* __restrict__ bf0, const float* __restrict__ bs0,
                            const float* __restrict__ Wf1, const float* __restrict__ Ws1,
                            const float* __restrict__ bf1, const float* __restrict__ bs1) {
    int stride = gridDim.x * blockDim.x;
    int gid = blockIdx.x * blockDim.x + threadIdx.x;
    for (int i = gid; i < 2 * 64 * 144; i += stride) {
        int l = i / 9216; int r = i % 9216; int j = r / 144; int k = r % 144;
        const float* Wf = l ? Wf1 : Wf0;
        const float* Ws = l ? Ws1 : Ws0;
        float wf = Wf[j * 144 + k], ws = Ws[j * 144 + k];
        if (k < 64) {
            d_Wnode[l][k * 256 + 2 * j]     = wf;
            d_Wnode[l][k * 256 + 2 * j + 1] = ws;
        } else if (k < 128) {
            int kk = k - 64;
            d_Wnode[l][kk * 256 + 128 + 2 * j]     = wf;
            d_Wnode[l][kk * 256 + 128 + 2 * j + 1] = ws;
        } else {
            int kk = k - 128;
            d_WqG[l][kk * 128 + 2 * j]     = wf;
            d_WqG[l][kk * 128 + 2 * j + 1] = ws;
        }
    }
    for (int i = gid; i < 2 * 64; i += stride) {
        int l = i >> 6; int j = i & 63;
        const float* bf = l ? bf1 : bf0;
        const float* bs = l ? bs1 : bs0;
        d_bias2[l][2 * j]           = bf[j];
        d_bias2[l][2 * j + 1]       = bs[j];
        d_bias2[l][128 + 2 * j]     = 0.f;
        d_bias2[l][128 + 2 * j + 1] = 0.f;
    }
}

// ---------------- node GEMM: P = in @ Wnode + bias; writes residual into y ----------------
__global__ __launch_bounds__(256, 2) void node_gemm_kernel(const float* __restrict__ x_in, int layer) {
    __shared__ __align__(16) float sX[64 * 68];
    __shared__ float sB[256];
    __shared__ float sSc[64], sSh[64];
    int t = threadIdx.x;
    int n0 = blockIdx.x * 64;
    const float* __restrict__ src = layer ? d_y0 : x_in;
    float* __restrict__ y = layer ? d_y1 : d_y0;
    const float* __restrict__ Wn = d_Wnode[layer];

    sB[t] = d_bias2[layer][t];
    if (t < 64) {
        sSc[t] = layer ? d_scale[0][t] : 1.f;
        sSh[t] = layer ? d_shift[0][t] : 0.f;
    }
    __syncthreads();
    {
        int n = t >> 2, q = t & 3;
        int node = n0 + n;
        #pragma unroll
        for (int i = 0; i < 4; i++) {
            int k = q * 16 + i * 4;
            float4 v = make_float4(0.f, 0.f, 0.f, 0.f);
            if (node < N_NODES) v = *(const float4*)&src[(size_t)node * 64 + k];
            float4 w = make_float4(v.x * sSc[k + 0] + sSh[k + 0],
                                   v.y * sSc[k + 1] + sSh[k + 1],
                                   v.z * sSc[k + 2] + sSh[k + 2],
                                   v.w * sSc[k + 3] + sSh[k + 3]);
            sX[(k + 0) * 68 + n] = w.x;
            sX[(k + 1) * 68 + n] = w.y;
            sX[(k + 2) * 68 + n] = w.z;
            sX[(k + 3) * 68 + n] = w.w;
            if (node < N_NODES) *(float4*)&y[(size_t)node * 64 + k] = w;  // residual init
        }
    }
    __syncthreads();

    int tx = t & 31, ty = t >> 5;
    float acc[8][8];
    #pragma unroll
    for (int e = 0; e < 8; e++)
        #pragma unroll
        for (int j = 0; j < 8; j++) acc[e][j] = 0.f;

    #pragma unroll 8
    for (int k = 0; k < 64; k++) {
        float4 w0 = *(const float4*)&Wn[k * 256 + tx * 8];
        float4 w1 = *(const float4*)&Wn[k * 256 + tx * 8 + 4];
        float4 z0 = *(const float4*)&sX[k * 68 + ty * 8];
        float4 z1 = *(const float4*)&sX[k * 68 + ty * 8 + 4];
        float ww[8] = {w0.x, w0.y, w0.z, w0.w, w1.x, w1.y, w1.z, w1.w};
        float zz[8] = {z0.x, z0.y, z0.z, z0.w, z1.x, z1.y, z1.z, z1.w};
        #pragma unroll
        for (int e = 0; e < 8; e++)
            #pragma unroll
            for (int j = 0; j < 8; j++) acc[e][j] += zz[e] * ww[j];
    }

    float b[8];
    #pragma unroll
    for (int j = 0; j < 8; j++) b[j] = sB[tx * 8 + j];
    #pragma unroll
    for (int e = 0; e < 8; e++) {
        int node = n0 + ty * 8 + e;
        if (node < N_NODES) {
            float4 o0 = make_float4(acc[e][0] + b[0], acc[e][1] + b[1], acc[e][2] + b[2], acc[e][3] + b[3]);
            float4 o1 = make_float4(acc[e][4] + b[4], acc[e][5] + b[5], acc[e][6] + b[6], acc[e][7] + b[7]);
            *(float4*)&d_P[(size_t)node * 256 + tx * 8]     = o0;
            *(float4*)&d_P[(size_t)node * 256 + tx * 8 + 4] = o1;
        }
    }
}

// ---------------- fused edge kernel: 64 edges/block ----------------
// Phase 1: Q-tile [64][128] = ea_tile @ WqG  -> shared memory (never global)
// Phase 2: warp = 8 edges, lane = 2 channels: gather P, add q, activations, red.v4
__global__ __launch_bounds__(256, 3) void edge_fused_kernel(const void* __restrict__ ei_raw,
                                                            const float* __restrict__ ea, int layer) {
    __shared__ __align__(16) float sQ[64 * 128];     // 32 KB  ({qf_c,qs_c} per edge)
    __shared__ __align__(16) float sW[16 * 128];     // 8 KB
    __shared__ __align__(16) float sEa[16][68];      // 4.25 KB  [k][edge]
    int t = threadIdx.x;
    int e0 = blockIdx.x * 64;
    const float* __restrict__ W = d_WqG[layer];
    float* __restrict__ y = layer ? d_y1 : d_y0;

    // stage weights (2048 floats) + ea tile (transposed)
    *(float4*)&sW[t * 8]     = *(const float4*)&W[t * 8];
    *(float4*)&sW[t * 8 + 4] = *(const float4*)&W[t * 8 + 4];
    {
        int e = t >> 2, q = t & 3;
        float4 v = *(const float4*)&ea[(size_t)(e0 + e) * 16 + q * 4];
        sEa[4 * q + 0][e] = v.x;
        sEa[4 * q + 1][e] = v.y;
        sEa[4 * q + 2][e] = v.z;
        sEa[4 * q + 3][e] = v.w;
    }
    __syncthreads();

    // phase 1: GEMM into sQ. thread = 4 edges x 8 outputs.
    {
        int o = (t & 15) * 8;
        int g = (t >> 4) * 4;
        uint64_t acc[4][4];
        #pragma unroll
        for (int e = 0; e < 4; e++)
            #pragma unroll
            for (int p = 0; p < 4; p++) acc[e][p] = 0;

        #pragma unroll
        for (int k = 0; k < 16; k++) {
            ulonglong2 w01 = *(const ulonglong2*)&sW[k * 128 + o];
            ulonglong2 w23 = *(const ulonglong2*)&sW[k * 128 + o + 4];
            #pragma unroll
            for (int e = 0; e < 4; e++) {
                float a = sEa[k][g + e];
                uint64_t aa = pack2(a, a);
                acc[e][0] = fma2(aa, w01.x, acc[e][0]);
                acc[e][1] = fma2(aa, w01.y, acc[e][1]);
                acc[e][2] = fma2(aa, w23.x, acc[e][2]);
                acc[e][3] = fma2(aa, w23.y, acc[e][3]);
            }
        }
        #pragma unroll
        for (int e = 0; e < 4; e++) {
            float2 a0 = unpack2(acc[e][0]), a1 = unpack2(acc[e][1]);
            float2 a2 = unpack2(acc[e][2]), a3 = unpack2(acc[e][3]);
            *(float4*)&sQ[(g + e) * 128 + o]     = make_float4(a0.x, a0.y, a1.x, a1.y);
            *(float4*)&sQ[(g + e) * 128 + o + 4] = make_float4(a2.x, a2.y, a3.x, a3.y);
        }
    }
    __syncthreads();

    // phase 2: warp handles 8 edges
    int warp = t >> 5, lane = t & 31;
    const int ei64 = d_ei64;
    const long long* eL = (const long long*)ei_raw;
    const int*       eI = (const int*)ei_raw;

    int sArr[8], dArr[8];
    #pragma unroll
    for (int i = 0; i < 8; i++) {
        int e = e0 + warp * 8 + i;
        int s, d;
        if (ei64) { s = (int)eL[e]; d = (int)eL[E_EDGES + e]; }
        else      { s = eI[e];      d = eI[E_EDGES + e]; }
        sArr[i] = min(max(s, 0), N_NODES - 1);
        dArr[i] = min(max(d, 0), N_NODES - 1);
    }

    // software pipeline over the 8 edges
    float4 dp = *(const float4*)&d_P[(size_t)dArr[0] * 256 + lane * 4];
    float4 sp = *(const float4*)&d_P[(size_t)sArr[0] * 256 + 128 + lane * 4];
    #pragma unroll
    for (int i = 0; i < 8; i++) {
        float4 cdp = dp, csp = sp;
        if (i + 1 < 8) {
            dp = *(const float4*)&d_P[(size_t)dArr[i + 1] * 256 + lane * 4];
            sp = *(const float4*)&d_P[(size_t)sArr[i + 1] * 256 + 128 + lane * 4];
        }
        float4 q = *(const float4*)&sQ[(warp * 8 + i) * 128 + lane * 4];

        float fa = cdp.x + csp.x + q.x;
        float sa = cdp.y + csp.y + q.y;
        float fb = cdp.z + csp.z + q.z;
        float sb = cdp.w + csp.w + q.w;
        float ma = sigmoid_f(fa) * softplus_f(sa);
        float mb = sigmoid_f(fb) * softplus_f(sb);

        float m2 = __shfl_down_sync(0xFFFFFFFFu, ma, 1);
        float m3 = __shfl_down_sync(0xFFFFFFFFu, mb, 1);
        if ((lane & 1) == 0) {
            unsigned long long addr = (unsigned long long)(y + (size_t)dArr[i] * 64 + lane * 2);
            asm volatile("red.global.add.v4.f32 [%0], {%1, %2, %3, %4};"
                         :: "l"(addr), "f"(ma), "f"(mb), "f"(m2), "f"(m3) : "memory");
        }
    }
}

// ---------------- BN stats: fp32 per-block partials ----------------
__global__ __launch_bounds__(256) void stats_kernel(int layer) {
    __shared__ float ssum[256], ssq[256];
    const float* __restrict__ y = layer ? d_y1 : d_y0;
    int t = threadIdx.x;
    int c = t & 63, sub = t >> 6;
    float s = 0.f, q = 0.f;
    for (int r = blockIdx.x * 4 + sub; r < N_NODES; r += NB_STATS * 4) {
        float v = y[(size_t)r * 64 + c];
        s += v;
        q = fmaf(v, v, q);
    }
    ssum[t] = s; ssq[t] = q;
    __syncthreads();
    if (t < 128) { ssum[t] += ssum[t + 128]; ssq[t] += ssq[t + 128]; }
    __syncthreads();
    if (t < 64) {
        d_psum[blockIdx.x * 64 + c] = ssum[t] + ssum[t + 64];
        d_psq[blockIdx.x * 64 + c]  = ssq[t] + ssq[t + 64];
    }
}

__global__ void finalize_stats_kernel(int layer, const float* __restrict__ gamma,
                                      const float* __restrict__ beta) {
    int c = threadIdx.x;
    if (c < 64) {
        double s = 0.0, q = 0.0;
        for (int b = 0; b < NB_STATS; b++) {
            s += (double)d_psum[b * 64 + c];
            q += (double)d_psq[b * 64 + c];
        }
        double m = s / (double)N_NODES;
        double v = q / (double)N_NODES - m * m;
        double sc = (double)gamma[c] * rsqrt(v + 1e-5);
        d_scale[layer][c] = (float)sc;
        d_shift[layer][c] = (float)((double)beta[c] - m * sc);
    }
}

// BN(layer1) fused with global-mean-pool: one block per graph
__global__ __launch_bounds__(256) void pool_kernel(float* __restrict__ out) {
    __shared__ float sred[256];
    int g = blockIdx.x;
    int t = threadIdx.x;
    int c = t & 63, sub = t >> 6;
    int r0 = d_bound[g], r1 = d_bound[g + 1];
    float sc = d_scale[1][c], sh = d_shift[1][c];
    float acc = 0.f;
    for (int r = r0 + sub; r < r1; r += 4)
        acc += d_y1[(size_t)r * 64 + c] * sc + sh;
    sred[t] = acc;
    __syncthreads();
    if (t < 128) sred[t] += sred[t + 128];
    __syncthreads();
    if (t < 64) {
        float total = sred[t] + sred[t + 64];
        float cnt = (float)(r1 - r0);
        out[g * 64 + c] = total / fmaxf(cnt, 1.f);
    }
}

// ---------------- launch ----------------
extern "C" void kernel_launch(void* const* d_in, const int* in_sizes, int n_in,
                              void* d_out, int out_size) {
    const float* x     = (const float*)d_in[0];
    const void*  ei    = d_in[1];
    const float* ea    = (const float*)d_in[2];
    const void*  batch = d_in[3];
    const float *Wf0 = (const float*)d_in[4],  *bf0 = (const float*)d_in[5];
    const float *Ws0 = (const float*)d_in[6],  *bs0 = (const float*)d_in[7];
    const float *g0  = (const float*)d_in[8],  *be0 = (const float*)d_in[9];
    const float *Wf1 = (const float*)d_in[10], *bf1 = (const float*)d_in[11];
    const float *Ws1 = (const float*)d_in[12], *bs1 = (const float*)d_in[13];
    const float *g1  = (const float*)d_in[14], *be1 = (const float*)d_in[15];
    float* out = (float*)d_out;

    const int nodeBlocks = (N_NODES + 63) / 64;   // 782

    detect_bounds_kernel<<<1, 128>>>((const int*)ei, (const int*)batch);
    prep_kernel<<<72, 256>>>(Wf0, Ws0, bf0, bs0, Wf1, Ws1, bf1, bs1);

    // layer 0
    node_gemm_kernel<<<nodeBlocks, 256>>>(x, 0);
    edge_fused_kernel<<<NB_FUSED, 256>>>(ei, ea, 0);
    stats_kernel<<<NB_STATS, 256>>>(0);
    finalize_stats_kernel<<<1, 64>>>(0, g0, be0);

    // layer 1 (BN0 folded into node_gemm input + residual init)
    node_gemm_kernel<<<nodeBlocks, 256>>>(x, 1);
    edge_fused_kernel<<<NB_FUSED, 256>>>(ei, ea, 1);
    stats_kernel<<<NB_STATS, 256>>>(1);
    finalize_stats_kernel<<<1, 64>>>(1, g1, be1);

    // pool + output
    pool_kernel<<<64, 256>>>(out);
}

// round 14
// speedup vs baseline: 1.2934x; 1.0037x over previous
#include <cuda_runtime.h>
#include <cuda_bf16.h>
#include <cstdint>

#define N_NODES 50000
#define E_EDGES 800000
#define NB_STATS 240
#define NB_FUSED 12500   // 800000 / 64 edges per block

// ---------------- device scratch (static, no allocs) ----------------
// P layout per node (256 floats):
//   dst [0,128):   channel c -> {fd,sd} at offset 2c   (lane float4 at lane*4 = {fd_a,sd_a,fd_b,sd_b})
//   src [128,256): channel c -> {fs,ss} at offset 128+2c
__device__ __align__(16) float  d_P[(size_t)N_NODES * 256];
__device__ __align__(16) float  d_y0[(size_t)N_NODES * 64];
__device__ __align__(16) float  d_y1[(size_t)N_NODES * 64];
__device__ __align__(16) float  d_Wnode[2][64 * 256];
__device__ __align__(16) float  d_WqG[2][16 * 128];           // [k][2j]=wf, [k][2j+1]=ws
__device__ float  d_bias2[2][256];
__device__ float  d_psum[NB_STATS * 64];
__device__ float  d_psq[NB_STATS * 64];
__device__ __align__(16) float  d_scale[2][64];
__device__ __align__(16) float  d_shift[2][64];
__device__ int    d_bound[65];
__device__ int    d_ei64;

__device__ __forceinline__ float sigmoid_f(float x) {
    float t;
    asm("tanh.approx.f32 %0, %1;" : "=f"(t) : "f"(x * 0.5f));
    return fmaf(0.5f, t, 0.5f);
}
__device__ __forceinline__ float softplus_f(float x) {
    return (x > 20.f) ? x : __logf(1.f + __expf(x));
}
__device__ __forceinline__ uint64_t fma2(uint64_t a, uint64_t b, uint64_t c) {
    uint64_t d;
    asm("fma.rn.f32x2 %0, %1, %2, %3;" : "=l"(d) : "l"(a), "l"(b), "l"(c));
    return d;
}
__device__ __forceinline__ float2 unpack2(uint64_t v) {
    float2 r;
    asm("mov.b64 {%0, %1}, %2;" : "=f"(r.x), "=f"(r.y) : "l"(v));
    return r;
}
__device__ __forceinline__ uint64_t pack2(float a, float b) {
    uint64_t r;
    asm("mov.b64 %0, {%1, %2};" : "=l"(r) : "f"(a), "f"(b));
    return r;
}

// ---------------- dtype detection + graph bounds (1 block) ----------------
__global__ void detect_bounds_kernel(const int* __restrict__ ei32, const int* __restrict__ b32) {
    __shared__ int sb64;
    if (threadIdx.x == 0) {
        int o = 0;
        #pragma unroll
        for (int i = 1; i < 64; i += 2) o |= ei32[i];
        d_ei64 = (o == 0) ? 1 : 0;
        sb64 = (b32[N_NODES - 1] == 0) ? 1 : 0;
    }
    __syncthreads();
    int g = threadIdx.x;
    if (g <= 64) {
        int b64 = sb64;
        const long long* bL = (const long long*)b32;
        int lo = 0, hi = N_NODES;
        while (lo < hi) {
            int mid = (lo + hi) >> 1;
            long long bv = b64 ? bL[mid] : (long long)b32[mid];
            if (bv < (long long)g) lo = mid + 1; else hi = mid;
        }
        d_bound[g] = lo;
    }
}

// ---------------- prep: pack weights ----------------
__global__ void prep_kernel(const float* __restrict__ Wf0, const float* __restrict__ Ws0,
                            const float* __restrict__ bf0, const float* __restrict__ bs0,
                            const float* __restrict__ Wf1, const float* __restrict__ Ws1,
                            const float* __restrict__ bf1, const float* __restrict__ bs1) {
    int stride = gridDim.x * blockDim.x;
    int gid = blockIdx.x * blockDim.x + threadIdx.x;
    for (int i = gid; i < 2 * 64 * 144; i += stride) {
        int l = i / 9216; int r = i % 9216; int j = r / 144; int k = r % 144;
        const float* Wf = l ? Wf1 : Wf0;
        const float* Ws = l ? Ws1 : Ws0;
        float wf = Wf[j * 144 + k], ws = Ws[j * 144 + k];
        if (k < 64) {
            d_Wnode[l][k * 256 + 2 * j]     = wf;
            d_Wnode[l][k * 256 + 2 * j + 1] = ws;
        } else if (k < 128) {
            int kk = k - 64;
            d_Wnode[l][kk * 256 + 128 + 2 * j]     = wf;
            d_Wnode[l][kk * 256 + 128 + 2 * j + 1] = ws;
        } else {
            int kk = k - 128;
            d_WqG[l][kk * 128 + 2 * j]     = wf;
            d_WqG[l][kk * 128 + 2 * j + 1] = ws;
        }
    }
    for (int i = gid; i < 2 * 64; i += stride) {
        int l = i >> 6; int j = i & 63;
        const float* bf = l ? bf1 : bf0;
        const float* bs = l ? bs1 : bs0;
        d_bias2[l][2 * j]           = bf[j];
        d_bias2[l][2 * j + 1]       = bs[j];
        d_bias2[l][128 + 2 * j]     = 0.f;
        d_bias2[l][128 + 2 * j + 1] = 0.f;
    }
}

// ---------------- node GEMM: P = in @ Wnode + bias; writes residual into y ----------------
__global__ __launch_bounds__(256, 2) void node_gemm_kernel(const float* __restrict__ x_in, int layer) {
    __shared__ __align__(16) float sX[64 * 68];
    __shared__ float sB[256];
    __shared__ float sSc[64], sSh[64];
    int t = threadIdx.x;
    int n0 = blockIdx.x * 64;
    const float* __restrict__ src = layer ? d_y0 : x_in;
    float* __restrict__ y = layer ? d_y1 : d_y0;
    const float* __restrict__ Wn = d_Wnode[layer];

    sB[t] = d_bias2[layer][t];
    if (t < 64) {
        sSc[t] = layer ? d_scale[0][t] : 1.f;
        sSh[t] = layer ? d_shift[0][t] : 0.f;
    }
    __syncthreads();
    {
        int n = t >> 2, q = t & 3;
        int node = n0 + n;
        #pragma unroll
        for (int i = 0; i < 4; i++) {
            int k = q * 16 + i * 4;
            float4 v = make_float4(0.f, 0.f, 0.f, 0.f);
            if (node < N_NODES) v = *(const float4*)&src[(size_t)node * 64 + k];
            float4 w = make_float4(v.x * sSc[k + 0] + sSh[k + 0],
                                   v.y * sSc[k + 1] + sSh[k + 1],
                                   v.z * sSc[k + 2] + sSh[k + 2],
                                   v.w * sSc[k + 3] + sSh[k + 3]);
            sX[(k + 0) * 68 + n] = w.x;
            sX[(k + 1) * 68 + n] = w.y;
            sX[(k + 2) * 68 + n] = w.z;
            sX[(k + 3) * 68 + n] = w.w;
            if (node < N_NODES) *(float4*)&y[(size_t)node * 64 + k] = w;  // residual init
        }
    }
    __syncthreads();

    int tx = t & 31, ty = t >> 5;
    float acc[8][8];
    #pragma unroll
    for (int e = 0; e < 8; e++)
        #pragma unroll
        for (int j = 0; j < 8; j++) acc[e][j] = 0.f;

    #pragma unroll 8
    for (int k = 0; k < 64; k++) {
        float4 w0 = *(const float4*)&Wn[k * 256 + tx * 8];
        float4 w1 = *(const float4*)&Wn[k * 256 + tx * 8 + 4];
        float4 z0 = *(const float4*)&sX[k * 68 + ty * 8];
        float4 z1 = *(const float4*)&sX[k * 68 + ty * 8 + 4];
        float ww[8] = {w0.x, w0.y, w0.z, w0.w, w1.x, w1.y, w1.z, w1.w};
        float zz[8] = {z0.x, z0.y, z0.z, z0.w, z1.x, z1.y, z1.z, z1.w};
        #pragma unroll
        for (int e = 0; e < 8; e++)
            #pragma unroll
            for (int j = 0; j < 8; j++) acc[e][j] += zz[e] * ww[j];
    }

    float b[8];
    #pragma unroll
    for (int j = 0; j < 8; j++) b[j] = sB[tx * 8 + j];
    #pragma unroll
    for (int e = 0; e < 8; e++) {
        int node = n0 + ty * 8 + e;
        if (node < N_NODES) {
            float4 o0 = make_float4(acc[e][0] + b[0], acc[e][1] + b[1], acc[e][2] + b[2], acc[e][3] + b[3]);
            float4 o1 = make_float4(acc[e][4] + b[4], acc[e][5] + b[5], acc[e][6] + b[6], acc[e][7] + b[7]);
            *(float4*)&d_P[(size_t)node * 256 + tx * 8]     = o0;
            *(float4*)&d_P[(size_t)node * 256 + tx * 8 + 4] = o1;
        }
    }
}

// ---------------- fused edge kernel: 64 edges/block ----------------
// Phase 1: Q-tile [64][128] = ea_tile @ WqG  -> shared memory (never global)
// Phase 2: warp = 8 edges, lane = 2 channels: gather P, add q, activations, red.v4
__global__ __launch_bounds__(256, 3) void edge_fused_kernel(const void* __restrict__ ei_raw,
                                                            const float* __restrict__ ea, int layer) {
    __shared__ __align__(16) float sQ[64 * 128];     // 32 KB  ({qf_c,qs_c} per edge)
    __shared__ __align__(16) float sW[16 * 128];     // 8 KB
    __shared__ __align__(16) float sEa[16][68];      // 4.25 KB  [k][edge]
    int t = threadIdx.x;
    int e0 = blockIdx.x * 64;
    const float* __restrict__ W = d_WqG[layer];
    float* __restrict__ y = layer ? d_y1 : d_y0;

    // stage weights (2048 floats) + ea tile (transposed)
    *(float4*)&sW[t * 8]     = *(const float4*)&W[t * 8];
    *(float4*)&sW[t * 8 + 4] = *(const float4*)&W[t * 8 + 4];
    {
        int e = t >> 2, q = t & 3;
        float4 v = *(const float4*)&ea[(size_t)(e0 + e) * 16 + q * 4];
        sEa[4 * q + 0][e] = v.x;
        sEa[4 * q + 1][e] = v.y;
        sEa[4 * q + 2][e] = v.z;
        sEa[4 * q + 3][e] = v.w;
    }
    __syncthreads();

    // phase 1: GEMM into sQ. thread = 4 edges x 8 outputs.
    {
        int o = (t & 15) * 8;
        int g = (t >> 4) * 4;
        uint64_t acc[4][4];
        #pragma unroll
        for (int e = 0; e < 4; e++)
            #pragma unroll
            for (int p = 0; p < 4; p++) acc[e][p] = 0;

        #pragma unroll
        for (int k = 0; k < 16; k++) {
            ulonglong2 w01 = *(const ulonglong2*)&sW[k * 128 + o];
            ulonglong2 w23 = *(const ulonglong2*)&sW[k * 128 + o + 4];
            #pragma unroll
            for (int e = 0; e < 4; e++) {
                float a = sEa[k][g + e];
                uint64_t aa = pack2(a, a);
                acc[e][0] = fma2(aa, w01.x, acc[e][0]);
                acc[e][1] = fma2(aa, w01.y, acc[e][1]);
                acc[e][2] = fma2(aa, w23.x, acc[e][2]);
                acc[e][3] = fma2(aa, w23.y, acc[e][3]);
            }
        }
        #pragma unroll
        for (int e = 0; e < 4; e++) {
            float2 a0 = unpack2(acc[e][0]), a1 = unpack2(acc[e][1]);
            float2 a2 = unpack2(acc[e][2]), a3 = unpack2(acc[e][3]);
            *(float4*)&sQ[(g + e) * 128 + o]     = make_float4(a0.x, a0.y, a1.x, a1.y);
            *(float4*)&sQ[(g + e) * 128 + o + 4] = make_float4(a2.x, a2.y, a3.x, a3.y);
        }
    }
    __syncthreads();

    // phase 2: warp handles 8 edges
    int warp = t >> 5, lane = t & 31;
    const int ei64 = d_ei64;
    const long long* eL = (const long long*)ei_raw;
    const int*       eI = (const int*)ei_raw;

    int sArr[8], dArr[8];
    #pragma unroll
    for (int i = 0; i < 8; i++) {
        int e = e0 + warp * 8 + i;
        int s, d;
        if (ei64) { s = (int)eL[e]; d = (int)eL[E_EDGES + e]; }
        else      { s = eI[e];      d = eI[E_EDGES + e]; }
        sArr[i] = min(max(s, 0), N_NODES - 1);
        dArr[i] = min(max(d, 0), N_NODES - 1);
    }

    // software pipeline over the 8 edges
    float4 dp = *(const float4*)&d_P[(size_t)dArr[0] * 256 + lane * 4];
    float4 sp = *(const float4*)&d_P[(size_t)sArr[0] * 256 + 128 + lane * 4];
    #pragma unroll
    for (int i = 0; i < 8; i++) {
        float4 cdp = dp, csp = sp;
        if (i + 1 < 8) {
            dp = *(const float4*)&d_P[(size_t)dArr[i + 1] * 256 + lane * 4];
            sp = *(const float4*)&d_P[(size_t)sArr[i + 1] * 256 + 128 + lane * 4];
        }
        float4 q = *(const float4*)&sQ[(warp * 8 + i) * 128 + lane * 4];

        float fa = cdp.x + csp.x + q.x;
        float sa = cdp.y + csp.y + q.y;
        float fb = cdp.z + csp.z + q.z;
        float sb = cdp.w + csp.w + q.w;
        float ma = sigmoid_f(fa) * softplus_f(sa);
        float mb = sigmoid_f(fb) * softplus_f(sb);

        float m2 = __shfl_down_sync(0xFFFFFFFFu, ma, 1);
        float m3 = __shfl_down_sync(0xFFFFFFFFu, mb, 1);
        if ((lane & 1) == 0) {
            unsigned long long addr = (unsigned long long)(y + (size_t)dArr[i] * 64 + lane * 2);
            asm volatile("red.global.add.v4.f32 [%0], {%1, %2, %3, %4};"
                         :: "l"(addr), "f"(ma), "f"(mb), "f"(m2), "f"(m3) : "memory");
        }
    }
}

// ---------------- BN stats: fp32 per-block partials ----------------
__global__ __launch_bounds__(256) void stats_kernel(int layer) {
    __shared__ float ssum[256], ssq[256];
    const float* __restrict__ y = layer ? d_y1 : d_y0;
    int t = threadIdx.x;
    int c = t & 63, sub = t >> 6;
    float s = 0.f, q = 0.f;
    for (int r = blockIdx.x * 4 + sub; r < N_NODES; r += NB_STATS * 4) {
        float v = y[(size_t)r * 64 + c];
        s += v;
        q = fmaf(v, v, q);
    }
    ssum[t] = s; ssq[t] = q;
    __syncthreads();
    if (t < 128) { ssum[t] += ssum[t + 128]; ssq[t] += ssq[t + 128]; }
    __syncthreads();
    if (t < 64) {
        d_psum[blockIdx.x * 64 + c] = ssum[t] + ssum[t + 64];
        d_psq[blockIdx.x * 64 + c]  = ssq[t] + ssq[t + 64];
    }
}

__global__ void finalize_stats_kernel(int layer, const float* __restrict__ gamma,
                                      const float* __restrict__ beta) {
    int c = threadIdx.x;
    if (c < 64) {
        double s = 0.0, q = 0.0;
        for (int b = 0; b < NB_STATS; b++) {
            s += (double)d_psum[b * 64 + c];
            q += (double)d_psq[b * 64 + c];
        }
        double m = s / (double)N_NODES;
        double v = q / (double)N_NODES - m * m;
        double sc = (double)gamma[c] * rsqrt(v + 1e-5);
        d_scale[layer][c] = (float)sc;
        d_shift[layer][c] = (float)((double)beta[c] - m * sc);
    }
}

// BN(layer1) fused with global-mean-pool: one block per graph
__global__ __launch_bounds__(256) void pool_kernel(float* __restrict__ out) {
    __shared__ float sred[256];
    int g = blockIdx.x;
    int t = threadIdx.x;
    int c = t & 63, sub = t >> 6;
    int r0 = d_bound[g], r1 = d_bound[g + 1];
    float sc = d_scale[1][c], sh = d_shift[1][c];
    float acc = 0.f;
    for (int r = r0 + sub; r < r1; r += 4)
        acc += d_y1[(size_t)r * 64 + c] * sc + sh;
    sred[t] = acc;
    __syncthreads();
    if (t < 128) sred[t] += sred[t + 128];
    __syncthreads();
    if (t < 64) {
        float total = sred[t] + sred[t + 64];
        float cnt = (float)(r1 - r0);
        out[g * 64 + c] = total / fmaxf(cnt, 1.f);
    }
}

// ---------------- launch ----------------
extern "C" void kernel_launch(void* const* d_in, const int* in_sizes, int n_in,
                              void* d_out, int out_size) {
    const float* x     = (const float*)d_in[0];
    const void*  ei    = d_in[1];
    const float* ea    = (const float*)d_in[2];
    const void*  batch = d_in[3];
    const float *Wf0 = (const float*)d_in[4],  *bf0 = (const float*)d_in[5];
    const float *Ws0 = (const float*)d_in[6],  *bs0 = (const float*)d_in[7];
    const float *g0  = (const float*)d_in[8],  *be0 = (const float*)d_in[9];
    const float *Wf1 = (const float*)d_in[10], *bf1 = (const float*)d_in[11];
    const float *Ws1 = (const float*)d_in[12], *bs1 = (const float*)d_in[13];
    const float *g1  = (const float*)d_in[14], *be1 = (const float*)d_in[15];
    float* out = (float*)d_out;

    const int nodeBlocks = (N_NODES + 63) / 64;   // 782

    detect_bounds_kernel<<<1, 128>>>((const int*)ei, (const int*)batch);
    prep_kernel<<<72, 256>>>(Wf0, Ws0, bf0, bs0, Wf1, Ws1, bf1, bs1);

    // layer 0
    node_gemm_kernel<<<nodeBlocks, 256>>>(x, 0);
    edge_fused_kernel<<<NB_FUSED, 256>>>(ei, ea, 0);
    stats_kernel<<<NB_STATS, 256>>>(0);
    finalize_stats_kernel<<<1, 64>>>(0, g0, be0);

    // layer 1 (BN0 folded into node_gemm input + residual init)
    node_gemm_kernel<<<nodeBlocks, 256>>>(x, 1);
    edge_fused_kernel<<<NB_FUSED, 256>>>(ei, ea, 1);
    stats_kernel<<<NB_STATS, 256>>>(1);
    finalize_stats_kernel<<<1, 64>>>(1, g1, be1);

    // pool + output
    pool_kernel<<<64, 256>>>(out);
}